// round 1
// baseline (speedup 1.0000x reference)
#include <cuda_runtime.h>
#include <cuda_bf16.h>

// Problem constants (fixed by the dataset)
#define NB   4
#define LL   4096
#define HH   16
#define DD   64
#define MM   64
#define CC   128
#define GG   32          // LL / CC
#define NTILE (NB*GG*HH) // 2048
#define EPS  1e-6f

// Smem row strides (padding to avoid bank conflicts on column access)
#define QS 68            // stride for 64-wide tiles
#define SS 132           // stride for 128-wide S tile

// Scratch: per-chunk KV states and key-sums + their exclusive prefixes.
__device__ float g_kv [NTILE * DD * MM]; // [n,g,h][d][m]
__device__ float g_kvp[NTILE * DD * MM];
__device__ float g_ks [NTILE * DD];
__device__ float g_ksp[NTILE * DD];

__device__ __forceinline__ float phi(float x) {
    // elu(x)+1
    return x > 0.f ? x + 1.f : __expf(x);
}

// ---------------------------------------------------------------------------
// Kernel 1: per-chunk state  kv[d][m] = sum_c phi(k[c][d]) * v[c][m]
//           and ksum[d] = sum_c phi(k[c][d])
// grid: NTILE blocks of 128 threads. smem: 2 * 128*QS floats.
// ---------------------------------------------------------------------------
__global__ __launch_bounds__(128, 1)
void k_state(const float* __restrict__ K, const float* __restrict__ V) {
    extern __shared__ float sm[];
    float* sk = sm;               // 128*QS (phi applied)
    float* sv = sm + CC * QS;     // 128*QS
    const int b   = blockIdx.x;
    const int h   = b & 15;
    const int g   = (b >> 4) & 31;
    const int n   = b >> 9;
    const int tid = threadIdx.x;

    // Load K (with phi) and V tiles: 2048 float4 each, 16 per thread
    #pragma unroll
    for (int it = 0; it < 16; it++) {
        int idx = tid + it * 128;     // 0..2047
        int r   = idx >> 4;           // row 0..127
        int cv  = idx & 15;           // float4 within row
        int gbase = ((n * LL + g * CC + r) * HH + h) * DD + cv * 4;
        float4 k4 = *(const float4*)&K[gbase];
        float4 v4 = *(const float4*)&V[gbase];
        float* dk = &sk[r * QS + cv * 4];
        dk[0] = phi(k4.x); dk[1] = phi(k4.y); dk[2] = phi(k4.z); dk[3] = phi(k4.w);
        *(float4*)&sv[r * QS + cv * 4] = v4;
    }
    __syncthreads();

    // Each thread: 4 (d) x 8 (m) tile of the 64x64 state
    const int d0 = (tid >> 3) * 4;
    const int m0 = (tid & 7) * 8;
    float acc[4][8];
    #pragma unroll
    for (int i = 0; i < 4; i++)
        #pragma unroll
        for (int j = 0; j < 8; j++) acc[i][j] = 0.f;

    for (int c = 0; c < CC; c++) {
        float ka[4];
        #pragma unroll
        for (int i = 0; i < 4; i++) ka[i] = sk[c * QS + d0 + i];
        float4 v0 = *(const float4*)&sv[c * QS + m0];
        float4 v1 = *(const float4*)&sv[c * QS + m0 + 4];
        float vb[8] = {v0.x, v0.y, v0.z, v0.w, v1.x, v1.y, v1.z, v1.w};
        #pragma unroll
        for (int i = 0; i < 4; i++)
            #pragma unroll
            for (int j = 0; j < 8; j++) acc[i][j] += ka[i] * vb[j];
    }

    float* dst = &g_kv[(size_t)b * (DD * MM)];
    #pragma unroll
    for (int i = 0; i < 4; i++) {
        *(float4*)&dst[(d0 + i) * MM + m0]     = make_float4(acc[i][0], acc[i][1], acc[i][2], acc[i][3]);
        *(float4*)&dst[(d0 + i) * MM + m0 + 4] = make_float4(acc[i][4], acc[i][5], acc[i][6], acc[i][7]);
    }

    if (tid < DD) {
        float s = 0.f;
        for (int c = 0; c < CC; c++) s += sk[c * QS + tid];
        g_ks[(size_t)b * DD + tid] = s;
    }
}

// ---------------------------------------------------------------------------
// Kernel 2: exclusive prefix over g for kv and ksum, per (n,h).
// grid: NB*HH = 64 blocks of 256 threads.
// ---------------------------------------------------------------------------
__global__ __launch_bounds__(256, 1)
void k_scan() {
    const int nh = blockIdx.x;      // n*HH + h
    const int n  = nh >> 4;
    const int h  = nh & 15;
    const int tid = threadIdx.x;

    float acc[16];
    #pragma unroll
    for (int ii = 0; ii < 16; ii++) acc[ii] = 0.f;
    for (int g = 0; g < GG; g++) {
        size_t base = ((size_t)((n * GG + g) * HH + h)) * (DD * MM);
        #pragma unroll
        for (int ii = 0; ii < 16; ii++) {
            int pos = tid + ii * 256;
            g_kvp[base + pos] = acc[ii];
            acc[ii] += g_kv[base + pos];
        }
    }

    if (tid < DD) {
        float a = 0.f;
        for (int g = 0; g < GG; g++) {
            size_t off = (size_t)((n * GG + g) * HH + h) * DD + tid;
            g_ksp[off] = a;
            a += g_ks[off];
        }
    }
}

// ---------------------------------------------------------------------------
// Kernel 3: per-tile fused attention.
// grid: NTILE blocks of 256 threads.
// smem: q,k,v tiles (stride QS), S (128 x SS), kv_prev (64 x QS), ksum_prev, z.
// ---------------------------------------------------------------------------
#define SM3_FLOATS (3*CC*QS + CC*SS + DD*QS + DD + CC)

__global__ __launch_bounds__(256, 1)
void k_main(const float* __restrict__ Q, const float* __restrict__ K,
            const float* __restrict__ V, float* __restrict__ O) {
    extern __shared__ float sm[];
    float* sq   = sm;                       // 128*QS (phi applied)
    float* sk   = sq + CC * QS;             // 128*QS (phi applied)
    float* sv   = sk + CC * QS;             // 128*QS
    float* sS   = sv + CC * QS;             // 128*SS
    float* skvp = sS + CC * SS;             // 64*QS
    float* sksp = skvp + DD * QS;           // 64
    float* sz   = sksp + DD;                // 128

    const int b   = blockIdx.x;
    const int h   = b & 15;
    const int g   = (b >> 4) & 31;
    const int n   = b >> 9;
    const int tid = threadIdx.x;

    // --- Load q (phi), k (phi), v tiles ---
    #pragma unroll
    for (int it = 0; it < 8; it++) {
        int idx = tid + it * 256;     // 0..2047
        int r   = idx >> 4;
        int cv  = idx & 15;
        int gbase = ((n * LL + g * CC + r) * HH + h) * DD + cv * 4;
        float4 q4 = *(const float4*)&Q[gbase];
        float4 k4 = *(const float4*)&K[gbase];
        float4 v4 = *(const float4*)&V[gbase];
        float* dq = &sq[r * QS + cv * 4];
        dq[0] = phi(q4.x); dq[1] = phi(q4.y); dq[2] = phi(q4.z); dq[3] = phi(q4.w);
        float* dk = &sk[r * QS + cv * 4];
        dk[0] = phi(k4.x); dk[1] = phi(k4.y); dk[2] = phi(k4.z); dk[3] = phi(k4.w);
        *(float4*)&sv[r * QS + cv * 4] = v4;
    }
    // kv_prev: 1024 float4
    {
        const float* src = &g_kvp[(size_t)b * (DD * MM)];
        #pragma unroll
        for (int it = 0; it < 4; it++) {
            int idx = tid + it * 256;     // 0..1023
            int d   = idx >> 4;
            int cv  = idx & 15;
            *(float4*)&skvp[d * QS + cv * 4] = *(const float4*)&src[d * MM + cv * 4];
        }
    }
    if (tid < DD) sksp[tid] = g_ksp[(size_t)b * DD + tid];
    __syncthreads();

    // --- S = tril( phi(q) @ phi(k)^T ), 8x8 register tile per thread ---
    {
        const int l0 = (tid >> 4) * 8;  // 16 row groups
        const int k0 = (tid & 15) * 8;  // 16 col groups
        float acc[8][8];
        #pragma unroll
        for (int i = 0; i < 8; i++)
            #pragma unroll
            for (int j = 0; j < 8; j++) acc[i][j] = 0.f;

        for (int d = 0; d < DD; d += 4) {
            float4 a[8], bb[8];
            #pragma unroll
            for (int i = 0; i < 8; i++) a[i]  = *(const float4*)&sq[(l0 + i) * QS + d];
            #pragma unroll
            for (int j = 0; j < 8; j++) bb[j] = *(const float4*)&sk[(k0 + j) * QS + d];
            #pragma unroll
            for (int i = 0; i < 8; i++)
                #pragma unroll
                for (int j = 0; j < 8; j++) {
                    acc[i][j] += a[i].x * bb[j].x;
                    acc[i][j] += a[i].y * bb[j].y;
                    acc[i][j] += a[i].z * bb[j].z;
                    acc[i][j] += a[i].w * bb[j].w;
                }
        }
        #pragma unroll
        for (int i = 0; i < 8; i++)
            #pragma unroll
            for (int j = 0; j < 8; j++)
                sS[(l0 + i) * SS + k0 + j] = (l0 + i >= k0 + j) ? acc[i][j] : 0.f;
    }
    __syncthreads();

    // --- z[l] = rowsum(S[l]) + phi(q)[l] . ksum_prev + EPS ---
    if (tid < CC) {
        float zz = EPS;
        for (int k = 0; k < CC; k++) zz += sS[tid * SS + k];
        for (int d = 0; d < DD; d++) zz += sq[tid * QS + d] * sksp[d];
        sz[tid] = zz;
    }
    __syncthreads();

    // --- out = (S @ v + phi(q) @ kv_prev) / z ---
    {
        const int l0 = (tid >> 3) * 4;  // 32 row groups of 4
        const int m0 = (tid & 7) * 8;   // 8 col groups of 8
        float o[4][8];
        #pragma unroll
        for (int i = 0; i < 4; i++)
            #pragma unroll
            for (int j = 0; j < 8; j++) o[i][j] = 0.f;

        for (int k = 0; k < CC; k++) {
            float a[4];
            #pragma unroll
            for (int i = 0; i < 4; i++) a[i] = sS[(l0 + i) * SS + k];
            float4 v0 = *(const float4*)&sv[k * QS + m0];
            float4 v1 = *(const float4*)&sv[k * QS + m0 + 4];
            float vb[8] = {v0.x, v0.y, v0.z, v0.w, v1.x, v1.y, v1.z, v1.w};
            #pragma unroll
            for (int i = 0; i < 4; i++)
                #pragma unroll
                for (int j = 0; j < 8; j++) o[i][j] += a[i] * vb[j];
        }
        for (int d = 0; d < DD; d++) {
            float a[4];
            #pragma unroll
            for (int i = 0; i < 4; i++) a[i] = sq[(l0 + i) * QS + d];
            float4 v0 = *(const float4*)&skvp[d * QS + m0];
            float4 v1 = *(const float4*)&skvp[d * QS + m0 + 4];
            float vb[8] = {v0.x, v0.y, v0.z, v0.w, v1.x, v1.y, v1.z, v1.w};
            #pragma unroll
            for (int i = 0; i < 4; i++)
                #pragma unroll
                for (int j = 0; j < 8; j++) o[i][j] += a[i] * vb[j];
        }

        #pragma unroll
        for (int i = 0; i < 4; i++) {
            float invz = 1.f / sz[l0 + i];
            int gbase = ((n * LL + g * CC + l0 + i) * HH + h) * MM + m0;
            *(float4*)&O[gbase]     = make_float4(o[i][0]*invz, o[i][1]*invz, o[i][2]*invz, o[i][3]*invz);
            *(float4*)&O[gbase + 4] = make_float4(o[i][4]*invz, o[i][5]*invz, o[i][6]*invz, o[i][7]*invz);
        }
    }
}

// ---------------------------------------------------------------------------
extern "C" void kernel_launch(void* const* d_in, const int* in_sizes, int n_in,
                              void* d_out, int out_size) {
    const float* Q = (const float*)d_in[0];
    const float* K = (const float*)d_in[1];
    const float* V = (const float*)d_in[2];
    float* O = (float*)d_out;

    const int smem1 = 2 * CC * QS * sizeof(float);
    const int smem3 = SM3_FLOATS * sizeof(float);
    cudaFuncSetAttribute(k_state, cudaFuncAttributeMaxDynamicSharedMemorySize, smem1);
    cudaFuncSetAttribute(k_main,  cudaFuncAttributeMaxDynamicSharedMemorySize, smem3);

    k_state<<<NTILE, 128, smem1>>>(K, V);
    k_scan<<<NB * HH, 256>>>();
    k_main<<<NTILE, 256, smem3>>>(Q, K, V, O);
}

// round 4
// speedup vs baseline: 3.0275x; 3.0275x over previous
#include <cuda_runtime.h>
#include <cstdint>

#define NB 4
#define LL 4096
#define HH 16
#define DD 64
#define MM 64
#define CC 128
#define GG 32
#define NTILE (NB*GG*HH)   // 2048
#define EPS 1e-6f

// smem strides (floats), chosen per access pattern for conflict-free frag loads
#define SA 68   // row-pattern A/B loads (sq, sk in k_main)
#define SB 72   // col-pattern loads (sv, skvp in k_main; sk, sv in k_state)
#define SSW 132 // S tile stride

__device__ float g_kv [NTILE*DD*MM];
__device__ float g_kvp[NTILE*DD*MM];
__device__ float g_ks [NTILE*DD];
__device__ float g_ksp[NTILE*DD];

__device__ __forceinline__ float phi(float x) { return x > 0.f ? x + 1.f : __expf(x); }
__device__ __forceinline__ float f2tf(float f) {
    uint32_t r; asm("cvt.rna.tf32.f32 %0, %1;" : "=r"(r) : "f"(f)); return __uint_as_float(r);
}
__device__ __forceinline__ void mma8(float c[4], uint32_t a0, uint32_t a1, uint32_t a2, uint32_t a3,
                                     uint32_t b0, uint32_t b1) {
    asm volatile("mma.sync.aligned.m16n8k8.row.col.f32.tf32.tf32.f32 "
                 "{%0,%1,%2,%3},{%4,%5,%6,%7},{%8,%9},{%0,%1,%2,%3};"
                 : "+f"(c[0]), "+f"(c[1]), "+f"(c[2]), "+f"(c[3])
                 : "r"(a0), "r"(a1), "r"(a2), "r"(a3), "r"(b0), "r"(b1));
}

// ---------------------------------------------------------------------------
// k_state: kv[d][m] = sum_c phi(k)[c][d] * v[c][m]   (M=64,N=64,K=128, tf32 mma)
//          ksum[d] = sum_c phi(k)[c][d]
// 128 threads, 3 CTAs/SM. smem: sk[128][SB], sv[128][SB].
// ---------------------------------------------------------------------------
#define SMEM1 (2 * CC * SB * 4)

__global__ __launch_bounds__(128, 3)
void k_state(const float* __restrict__ K, const float* __restrict__ V) {
    extern __shared__ float sm[];
    float* sk = sm;
    float* sv = sm + CC * SB;
    const int tid = threadIdx.x, wid = tid >> 5, lane = tid & 31;
    const int gid = lane >> 2, tg = lane & 3;
    const int b = blockIdx.x, h = b & 15, g = (b >> 4) & 31, n = b >> 9;

    #pragma unroll
    for (int it = 0; it < 16; it++) {
        int idx = tid + it * 128;
        int r = idx >> 4, c0 = (idx & 15) * 4;
        int gb = ((n * LL + g * CC + r) * HH + h) * DD + c0;
        float4 k4 = *(const float4*)(K + gb);
        float4 v4 = *(const float4*)(V + gb);
        sk[r * SB + c0 + 0] = f2tf(phi(k4.x));
        sk[r * SB + c0 + 1] = f2tf(phi(k4.y));
        sk[r * SB + c0 + 2] = f2tf(phi(k4.z));
        sk[r * SB + c0 + 3] = f2tf(phi(k4.w));
        sv[r * SB + c0 + 0] = f2tf(v4.x);
        sv[r * SB + c0 + 1] = f2tf(v4.y);
        sv[r * SB + c0 + 2] = f2tf(v4.z);
        sv[r * SB + c0 + 3] = f2tf(v4.w);
    }
    __syncthreads();

    if (tid < DD) {
        float s = 0.f;
        #pragma unroll 8
        for (int c = 0; c < CC; c++) s += sk[c * SB + tid];
        g_ks[(size_t)b * DD + tid] = s;
    }

    // GEMM: warp wid handles rows d0..d0+15, all 64 cols, K=128
    const int d0 = wid * 16;
    float cD[8][4];
    #pragma unroll
    for (int j = 0; j < 8; j++)
        #pragma unroll
        for (int q = 0; q < 4; q++) cD[j][q] = 0.f;

    #pragma unroll
    for (int kk = 0; kk < 16; kk++) {
        int kr = kk * 8 + tg;
        // A[d][c] = phi(k)[c][d] -> read sk[c][d]
        uint32_t a0 = __float_as_uint(sk[kr * SB + d0 + gid]);
        uint32_t a1 = __float_as_uint(sk[kr * SB + d0 + 8 + gid]);
        uint32_t a2 = __float_as_uint(sk[(kr + 4) * SB + d0 + gid]);
        uint32_t a3 = __float_as_uint(sk[(kr + 4) * SB + d0 + 8 + gid]);
        #pragma unroll
        for (int nj = 0; nj < 8; nj++) {
            uint32_t b0 = __float_as_uint(sv[kr * SB + nj * 8 + gid]);
            uint32_t b1 = __float_as_uint(sv[(kr + 4) * SB + nj * 8 + gid]);
            mma8(cD[nj], a0, a1, a2, a3, b0, b1);
        }
    }

    float* dst = g_kv + (size_t)b * (DD * MM);
    #pragma unroll
    for (int nj = 0; nj < 8; nj++) {
        int col = nj * 8 + 2 * tg;
        *(float2*)(dst + (d0 + gid) * MM + col)     = make_float2(cD[nj][0], cD[nj][1]);
        *(float2*)(dst + (d0 + 8 + gid) * MM + col) = make_float2(cD[nj][2], cD[nj][3]);
    }
}

// ---------------------------------------------------------------------------
// k_scan: exclusive prefix over g (elementwise) + ksum prefix. grid (64,4)x256.
// ---------------------------------------------------------------------------
__global__ __launch_bounds__(256, 4)
void k_scan() {
    const int nh = blockIdx.x, n = nh >> 4, h = nh & 15;
    const int pos = blockIdx.y * 1024 + threadIdx.x * 4;
    float4 acc = make_float4(0.f, 0.f, 0.f, 0.f);
    for (int g = 0; g < GG; g++) {
        size_t base = ((size_t)((n * GG + g) * HH + h)) * (DD * MM) + pos;
        float4 cur = *(const float4*)&g_kv[base];
        *(float4*)&g_kvp[base] = acc;
        acc.x += cur.x; acc.y += cur.y; acc.z += cur.z; acc.w += cur.w;
    }
    if (blockIdx.y == 0 && threadIdx.x < DD) {
        float a = 0.f;
        for (int g = 0; g < GG; g++) {
            size_t off = (size_t)((n * GG + g) * HH + h) * DD + threadIdx.x;
            g_ksp[off] = a;
            a += g_ks[off];
        }
    }
}

// ---------------------------------------------------------------------------
// k_main: fused per-tile attention via tf32 mma.sync.
// 256 threads (8 warps), 1 CTA/SM.
// ---------------------------------------------------------------------------
#define OFF_SQ   0
#define OFF_SK   (CC*SA)                 // 8704
#define OFF_SV   (OFF_SK + CC*SA)        // 17408
#define OFF_SS   (OFF_SV + CC*SB)        // 26624
#define OFF_KVP  (OFF_SS + CC*SSW)       // 43520
#define OFF_KSP  (OFF_KVP + DD*SB)       // 48128
#define OFF_ZP   (OFF_KSP + DD)          // 48192
#define OFF_Z    (OFF_ZP + 2*CC)         // 48448
#define SM3_FLOATS (OFF_Z + CC)          // 48576
#define SMEM3  (SM3_FLOATS * 4)

__global__ __launch_bounds__(256, 1)
void k_main(const float* __restrict__ Q, const float* __restrict__ K,
            const float* __restrict__ V, float* __restrict__ O) {
    extern __shared__ float sm[];
    float* sq   = sm + OFF_SQ;
    float* sk   = sm + OFF_SK;
    float* sv   = sm + OFF_SV;
    float* sS   = sm + OFF_SS;
    float* skvp = sm + OFF_KVP;
    float* sksp = sm + OFF_KSP;
    float* szp  = sm + OFF_ZP;
    float* sz   = sm + OFF_Z;

    const int tid = threadIdx.x, wid = tid >> 5, lane = tid & 31;
    const int gid = lane >> 2, tg = lane & 3;
    const int b = blockIdx.x, h = b & 15, g = (b >> 4) & 31, n = b >> 9;

    // ---- loads (phi + tf32 truncation) ----
    #pragma unroll
    for (int it = 0; it < 8; it++) {
        int idx = tid + it * 256;
        int r = idx >> 4, c0 = (idx & 15) * 4;
        int gb = ((n * LL + g * CC + r) * HH + h) * DD + c0;
        float4 q4 = *(const float4*)(Q + gb);
        float4 k4 = *(const float4*)(K + gb);
        float4 v4 = *(const float4*)(V + gb);
        sq[r * SA + c0 + 0] = f2tf(phi(q4.x));
        sq[r * SA + c0 + 1] = f2tf(phi(q4.y));
        sq[r * SA + c0 + 2] = f2tf(phi(q4.z));
        sq[r * SA + c0 + 3] = f2tf(phi(q4.w));
        sk[r * SA + c0 + 0] = f2tf(phi(k4.x));
        sk[r * SA + c0 + 1] = f2tf(phi(k4.y));
        sk[r * SA + c0 + 2] = f2tf(phi(k4.z));
        sk[r * SA + c0 + 3] = f2tf(phi(k4.w));
        sv[r * SB + c0 + 0] = f2tf(v4.x);
        sv[r * SB + c0 + 1] = f2tf(v4.y);
        sv[r * SB + c0 + 2] = f2tf(v4.z);
        sv[r * SB + c0 + 3] = f2tf(v4.w);
    }
    {
        const float* src = g_kvp + (size_t)b * (DD * MM);
        #pragma unroll
        for (int it = 0; it < 4; it++) {
            int idx = tid + it * 256;
            int d = idx >> 4, m0 = (idx & 15) * 4;
            float4 s4 = *(const float4*)(src + d * MM + m0);
            skvp[d * SB + m0 + 0] = f2tf(s4.x);
            skvp[d * SB + m0 + 1] = f2tf(s4.y);
            skvp[d * SB + m0 + 2] = f2tf(s4.z);
            skvp[d * SB + m0 + 3] = f2tf(s4.w);
        }
        if (tid < DD) sksp[tid] = g_ksp[(size_t)b * DD + tid];
    }
    __syncthreads();

    // ---- S = phi(q) @ phi(k)^T : warp tile 32 rows x 64 cols ----
    const int wm = wid >> 1, wn = wid & 1;
    const int r0 = wm * 32, cN0 = wn * 64;
    {
        float cS[2][8][4];
        #pragma unroll
        for (int mi = 0; mi < 2; mi++)
            #pragma unroll
            for (int nj = 0; nj < 8; nj++)
                #pragma unroll
                for (int q = 0; q < 4; q++) cS[mi][nj][q] = 0.f;

        #pragma unroll
        for (int kk = 0; kk < 8; kk++) {
            int kc = kk * 8 + tg;
            uint32_t a[2][4];
            #pragma unroll
            for (int mi = 0; mi < 2; mi++) {
                int ar = r0 + mi * 16;
                a[mi][0] = __float_as_uint(sq[(ar + gid) * SA + kc]);
                a[mi][1] = __float_as_uint(sq[(ar + 8 + gid) * SA + kc]);
                a[mi][2] = __float_as_uint(sq[(ar + gid) * SA + kc + 4]);
                a[mi][3] = __float_as_uint(sq[(ar + 8 + gid) * SA + kc + 4]);
            }
            #pragma unroll
            for (int nj = 0; nj < 8; nj++) {
                uint32_t b0 = __float_as_uint(sk[(cN0 + nj * 8 + gid) * SA + kc]);
                uint32_t b1 = __float_as_uint(sk[(cN0 + nj * 8 + gid) * SA + kc + 4]);
                mma8(cS[0][nj], a[0][0], a[0][1], a[0][2], a[0][3], b0, b1);
                mma8(cS[1][nj], a[1][0], a[1][1], a[1][2], a[1][3], b0, b1);
            }
        }

        // mask, rowsum partials, store masked S (tf32) to smem
        float zr[2][2] = {{0.f, 0.f}, {0.f, 0.f}};
        #pragma unroll
        for (int mi = 0; mi < 2; mi++) {
            int rlo = r0 + mi * 16 + gid, rhi = rlo + 8;
            #pragma unroll
            for (int nj = 0; nj < 8; nj++) {
                int c0 = cN0 + nj * 8 + 2 * tg, c1 = c0 + 1;
                float s0 = (c0 <= rlo) ? cS[mi][nj][0] : 0.f;
                float s1 = (c1 <= rlo) ? cS[mi][nj][1] : 0.f;
                float s2 = (c0 <= rhi) ? cS[mi][nj][2] : 0.f;
                float s3 = (c1 <= rhi) ? cS[mi][nj][3] : 0.f;
                zr[mi][0] += s0 + s1;
                zr[mi][1] += s2 + s3;
                *(float2*)&sS[rlo * SSW + c0] = make_float2(f2tf(s0), f2tf(s1));
                *(float2*)&sS[rhi * SSW + c0] = make_float2(f2tf(s2), f2tf(s3));
            }
            // reduce across the 4 lanes sharing a row (tg bits)
            #pragma unroll
            for (int half = 0; half < 2; half++) {
                float v = zr[mi][half];
                v += __shfl_xor_sync(0xffffffffu, v, 1);
                v += __shfl_xor_sync(0xffffffffu, v, 2);
                zr[mi][half] = v;
            }
            if (tg == 0) {
                szp[wn * CC + rlo] = zr[mi][0];
                szp[wn * CC + rhi] = zr[mi][1];
            }
        }
    }
    __syncthreads();

    // ---- z[l] = rowsums + q . ksum_prev + eps ----
    if (tid < CC) {
        float qd = EPS;
        #pragma unroll 8
        for (int d = 0; d < DD; d++) qd += sq[tid * SA + d] * sksp[d];
        sz[tid] = szp[tid] + szp[CC + tid] + qd;
    }

    // ---- O = S_masked @ V + phi(q) @ kvp : warp tile 32 rows x 32 cols ----
    const int oc0 = wn * 32;
    float cO[2][4][4];
    #pragma unroll
    for (int mi = 0; mi < 2; mi++)
        #pragma unroll
        for (int nj = 0; nj < 4; nj++)
            #pragma unroll
            for (int q = 0; q < 4; q++) cO[mi][nj][q] = 0.f;

    #pragma unroll
    for (int kk = 0; kk < 16; kk++) {
        int kc = kk * 8 + tg;
        uint32_t a[2][4];
        #pragma unroll
        for (int mi = 0; mi < 2; mi++) {
            int ar = r0 + mi * 16;
            a[mi][0] = __float_as_uint(sS[(ar + gid) * SSW + kc]);
            a[mi][1] = __float_as_uint(sS[(ar + 8 + gid) * SSW + kc]);
            a[mi][2] = __float_as_uint(sS[(ar + gid) * SSW + kc + 4]);
            a[mi][3] = __float_as_uint(sS[(ar + 8 + gid) * SSW + kc + 4]);
        }
        #pragma unroll
        for (int nj = 0; nj < 4; nj++) {
            uint32_t b0 = __float_as_uint(sv[kc * SB + oc0 + nj * 8 + gid]);
            uint32_t b1 = __float_as_uint(sv[(kc + 4) * SB + oc0 + nj * 8 + gid]);
            mma8(cO[0][nj], a[0][0], a[0][1], a[0][2], a[0][3], b0, b1);
            mma8(cO[1][nj], a[1][0], a[1][1], a[1][2], a[1][3], b0, b1);
        }
    }
    #pragma unroll
    for (int kk = 0; kk < 8; kk++) {
        int kc = kk * 8 + tg;
        uint32_t a[2][4];
        #pragma unroll
        for (int mi = 0; mi < 2; mi++) {
            int ar = r0 + mi * 16;
            a[mi][0] = __float_as_uint(sq[(ar + gid) * SA + kc]);
            a[mi][1] = __float_as_uint(sq[(ar + 8 + gid) * SA + kc]);
            a[mi][2] = __float_as_uint(sq[(ar + gid) * SA + kc + 4]);
            a[mi][3] = __float_as_uint(sq[(ar + 8 + gid) * SA + kc + 4]);
        }
        #pragma unroll
        for (int nj = 0; nj < 4; nj++) {
            uint32_t b0 = __float_as_uint(skvp[kc * SB + oc0 + nj * 8 + gid]);
            uint32_t b1 = __float_as_uint(skvp[(kc + 4) * SB + oc0 + nj * 8 + gid]);
            mma8(cO[0][nj], a[0][0], a[0][1], a[0][2], a[0][3], b0, b1);
            mma8(cO[1][nj], a[1][0], a[1][1], a[1][2], a[1][3], b0, b1);
        }
    }
    __syncthreads();   // sz visible to all

    // ---- epilogue: divide by z, store ----
    #pragma unroll
    for (int mi = 0; mi < 2; mi++) {
        int rlo = r0 + mi * 16 + gid, rhi = rlo + 8;
        float izlo = 1.f / sz[rlo];
        float izhi = 1.f / sz[rhi];
        float* oblo = O + ((size_t)((n * LL + g * CC + rlo) * HH + h)) * MM;
        float* obhi = O + ((size_t)((n * LL + g * CC + rhi) * HH + h)) * MM;
        #pragma unroll
        for (int nj = 0; nj < 4; nj++) {
            int c0 = oc0 + nj * 8 + 2 * tg;
            *(float2*)(oblo + c0) = make_float2(cO[mi][nj][0] * izlo, cO[mi][nj][1] * izlo);
            *(float2*)(obhi + c0) = make_float2(cO[mi][nj][2] * izhi, cO[mi][nj][3] * izhi);
        }
    }
}

// ---------------------------------------------------------------------------
extern "C" void kernel_launch(void* const* d_in, const int* in_sizes, int n_in,
                              void* d_out, int out_size) {
    const float* Q = (const float*)d_in[0];
    const float* K = (const float*)d_in[1];
    const float* V = (const float*)d_in[2];
    float* O = (float*)d_out;

    cudaFuncSetAttribute(k_state, cudaFuncAttributeMaxDynamicSharedMemorySize, SMEM1);
    cudaFuncSetAttribute(k_main,  cudaFuncAttributeMaxDynamicSharedMemorySize, SMEM3);

    k_state<<<NTILE, 128, SMEM1>>>(K, V);
    k_scan<<<dim3(NB * HH, 4), 256>>>();
    k_main<<<NTILE, 256, SMEM3>>>(Q, K, V, O);
}

// round 5
// speedup vs baseline: 3.7071x; 1.2245x over previous
#include <cuda_runtime.h>
#include <cstdint>

#define NB 4
#define LL 4096
#define HH 16
#define DD 64
#define MM 64
#define CC 128
#define GG 32
#define NTILE (NB*GG*HH)   // 2048
#define EPS 1e-6f

// smem strides (floats)
#define SA 68   // row-pattern A loads (sq, sk)
#define SB 72   // col-pattern B loads (sv, skvp; k_state tiles)
#define SSW 132 // S tile stride

__device__ float g_kv [NTILE*DD*MM];
__device__ float g_kvp[NTILE*DD*MM];
__device__ float g_ks [NTILE*DD];
__device__ float g_ksp[NTILE*DD];

__device__ __forceinline__ float phi(float x) { return x > 0.f ? x + 1.f : __expf(x); }
__device__ __forceinline__ float f2tf(float f) {
    uint32_t r; asm("cvt.rna.tf32.f32 %0, %1;" : "=r"(r) : "f"(f)); return __uint_as_float(r);
}
__device__ __forceinline__ void mma8(float c[4], uint32_t a0, uint32_t a1, uint32_t a2, uint32_t a3,
                                     uint32_t b0, uint32_t b1) {
    asm volatile("mma.sync.aligned.m16n8k8.row.col.f32.tf32.tf32.f32 "
                 "{%0,%1,%2,%3},{%4,%5,%6,%7},{%8,%9},{%0,%1,%2,%3};"
                 : "+f"(c[0]), "+f"(c[1]), "+f"(c[2]), "+f"(c[3])
                 : "r"(a0), "r"(a1), "r"(a2), "r"(a3), "r"(b0), "r"(b1));
}

// ---------------------------------------------------------------------------
// k_state: kv[d][m] = sum_c phi(k)[c][d] * v[c][m]  (M=64,N=64,K=128)
//          ksum[d] = sum_c phi(k)[c][d]
// 256 threads (8 warps, 16x32 warp tiles), 2 CTAs/SM.
// ---------------------------------------------------------------------------
#define SMEM1 ((2*CC*SB + 256) * 4)

__global__ __launch_bounds__(256, 2)
void k_state(const float* __restrict__ K, const float* __restrict__ V) {
    extern __shared__ float sm[];
    float* sk   = sm;
    float* sv   = sm + CC * SB;
    float* sred = sm + 2 * CC * SB;   // 4 x 64 partial ksums
    const int tid = threadIdx.x, wid = tid >> 5, lane = tid & 31;
    const int gid = lane >> 2, tg = lane & 3;
    const int b = blockIdx.x, h = b & 15, g = (b >> 4) & 31, n = b >> 9;

    #pragma unroll
    for (int it = 0; it < 8; it++) {
        int idx = tid + it * 256;
        int r = idx >> 4, c0 = (idx & 15) * 4;
        int gb = ((n * LL + g * CC + r) * HH + h) * DD + c0;
        float4 k4 = *(const float4*)(K + gb);
        float4 v4 = *(const float4*)(V + gb);
        sk[r * SB + c0 + 0] = f2tf(phi(k4.x));
        sk[r * SB + c0 + 1] = f2tf(phi(k4.y));
        sk[r * SB + c0 + 2] = f2tf(phi(k4.z));
        sk[r * SB + c0 + 3] = f2tf(phi(k4.w));
        sv[r * SB + c0 + 0] = f2tf(v4.x);
        sv[r * SB + c0 + 1] = f2tf(v4.y);
        sv[r * SB + c0 + 2] = f2tf(v4.z);
        sv[r * SB + c0 + 3] = f2tf(v4.w);
    }
    __syncthreads();

    // ksum partials: thread handles 32 rows of one d
    {
        int d = tid & 63, part = tid >> 6;
        float s = 0.f;
        #pragma unroll 8
        for (int c = part * 32; c < part * 32 + 32; c++) s += sk[c * SB + d];
        sred[part * 64 + d] = s;
    }

    // GEMM: warp tile rows d0..d0+15 (wm), cols oc..oc+31 (wn), K=128
    const int d0 = (wid >> 1) * 16, oc = (wid & 1) * 32;
    float cD[4][4];
    #pragma unroll
    for (int nj = 0; nj < 4; nj++)
        #pragma unroll
        for (int q = 0; q < 4; q++) cD[nj][q] = 0.f;

    #pragma unroll
    for (int kk = 0; kk < 16; kk++) {
        int kr = kk * 8 + tg;
        uint32_t a0 = __float_as_uint(sk[kr * SB + d0 + gid]);
        uint32_t a1 = __float_as_uint(sk[kr * SB + d0 + 8 + gid]);
        uint32_t a2 = __float_as_uint(sk[(kr + 4) * SB + d0 + gid]);
        uint32_t a3 = __float_as_uint(sk[(kr + 4) * SB + d0 + 8 + gid]);
        #pragma unroll
        for (int nj = 0; nj < 4; nj++) {
            uint32_t b0 = __float_as_uint(sv[kr * SB + oc + nj * 8 + gid]);
            uint32_t b1 = __float_as_uint(sv[(kr + 4) * SB + oc + nj * 8 + gid]);
            mma8(cD[nj], a0, a1, a2, a3, b0, b1);
        }
    }

    float* dst = g_kv + (size_t)b * (DD * MM);
    #pragma unroll
    for (int nj = 0; nj < 4; nj++) {
        int col = oc + nj * 8 + 2 * tg;
        *(float2*)(dst + (d0 + gid) * MM + col)     = make_float2(cD[nj][0], cD[nj][1]);
        *(float2*)(dst + (d0 + 8 + gid) * MM + col) = make_float2(cD[nj][2], cD[nj][3]);
    }

    __syncthreads();
    if (tid < 64)
        g_ks[(size_t)b * DD + tid] = sred[tid] + sred[64 + tid] + sred[128 + tid] + sred[192 + tid];
}

// ---------------------------------------------------------------------------
// k_scan: exclusive prefix over g (elementwise) + ksum prefix. grid (64,4)x256.
// ---------------------------------------------------------------------------
__global__ __launch_bounds__(256, 4)
void k_scan() {
    const int nh = blockIdx.x, n = nh >> 4, h = nh & 15;
    const int pos = blockIdx.y * 1024 + threadIdx.x * 4;
    float4 acc = make_float4(0.f, 0.f, 0.f, 0.f);
    for (int g = 0; g < GG; g++) {
        size_t base = ((size_t)((n * GG + g) * HH + h)) * (DD * MM) + pos;
        float4 cur = *(const float4*)&g_kv[base];
        *(float4*)&g_kvp[base] = acc;
        acc.x += cur.x; acc.y += cur.y; acc.z += cur.z; acc.w += cur.w;
    }
    if (blockIdx.y == 0 && threadIdx.x < DD) {
        float a = 0.f;
        for (int g = 0; g < GG; g++) {
            size_t off = (size_t)((n * GG + g) * HH + h) * DD + threadIdx.x;
            g_ksp[off] = a;
            a += g_ks[off];
        }
    }
}

// ---------------------------------------------------------------------------
// k_main: fused per-tile attention. 512 threads, warp-specialized:
//   warps 0-7 : S = tril(phi(q) phi(k)^T), rowsums, z
//   warps 8-15: O = phi(q) @ kvp  (overlapped with S)  + S @ V, epilogue
// ---------------------------------------------------------------------------
#define OFF_SQ   0
#define OFF_SK   (CC*SA)
#define OFF_SV   (OFF_SK + CC*SA)
#define OFF_SS   (OFF_SV + CC*SB)
#define OFF_KVP  (OFF_SS + CC*SSW)
#define OFF_KSP  (OFF_KVP + DD*SB)
#define OFF_ZP   (OFF_KSP + DD)
#define OFF_Z    (OFF_ZP + 2*CC)
#define SM3_FLOATS (OFF_Z + CC)
#define SMEM3  (SM3_FLOATS * 4)

__global__ __launch_bounds__(512, 1)
void k_main(const float* __restrict__ Q, const float* __restrict__ K,
            const float* __restrict__ V, float* __restrict__ O) {
    extern __shared__ float sm[];
    float* sq   = sm + OFF_SQ;
    float* sk   = sm + OFF_SK;
    float* sv   = sm + OFF_SV;
    float* sS   = sm + OFF_SS;
    float* skvp = sm + OFF_KVP;
    float* sksp = sm + OFF_KSP;
    float* szp  = sm + OFF_ZP;
    float* sz   = sm + OFF_Z;

    const int tid = threadIdx.x, wid = tid >> 5, lane = tid & 31;
    const int gid = lane >> 2, tg = lane & 3;
    const int b = blockIdx.x, h = b & 15, g = (b >> 4) & 31, n = b >> 9;

    // ---- loads (512 threads: 4 f4 per array per thread) ----
    #pragma unroll
    for (int it = 0; it < 4; it++) {
        int idx = tid + it * 512;
        int r = idx >> 4, c0 = (idx & 15) * 4;
        int gb = ((n * LL + g * CC + r) * HH + h) * DD + c0;
        float4 q4 = *(const float4*)(Q + gb);
        float4 k4 = *(const float4*)(K + gb);
        float4 v4 = *(const float4*)(V + gb);
        sq[r * SA + c0 + 0] = f2tf(phi(q4.x));
        sq[r * SA + c0 + 1] = f2tf(phi(q4.y));
        sq[r * SA + c0 + 2] = f2tf(phi(q4.z));
        sq[r * SA + c0 + 3] = f2tf(phi(q4.w));
        sk[r * SA + c0 + 0] = f2tf(phi(k4.x));
        sk[r * SA + c0 + 1] = f2tf(phi(k4.y));
        sk[r * SA + c0 + 2] = f2tf(phi(k4.z));
        sk[r * SA + c0 + 3] = f2tf(phi(k4.w));
        sv[r * SB + c0 + 0] = f2tf(v4.x);
        sv[r * SB + c0 + 1] = f2tf(v4.y);
        sv[r * SB + c0 + 2] = f2tf(v4.z);
        sv[r * SB + c0 + 3] = f2tf(v4.w);
    }
    {
        const float* src = g_kvp + (size_t)b * (DD * MM);
        #pragma unroll
        for (int it = 0; it < 2; it++) {
            int idx = tid + it * 512;
            int d = idx >> 4, m0 = (idx & 15) * 4;
            float4 s4 = *(const float4*)(src + d * MM + m0);
            skvp[d * SB + m0 + 0] = f2tf(s4.x);
            skvp[d * SB + m0 + 1] = f2tf(s4.y);
            skvp[d * SB + m0 + 2] = f2tf(s4.z);
            skvp[d * SB + m0 + 3] = f2tf(s4.w);
        }
        if (tid < DD) sksp[tid] = g_ksp[(size_t)b * DD + tid];
    }
    __syncthreads();   // (A)

    // O accumulators live in warps 8-15 across all phases
    float cO[2][4][4];
    const int widq = wid - 8;
    const int rq0 = (widq >> 1) * 32, ocq = (widq & 1) * 32;

    if (wid < 8) {
        // ---- S = phi(q) @ phi(k)^T : warp tile 32 rows x 64 cols ----
        const int r0 = (wid >> 1) * 32, cN0 = (wid & 1) * 64, wn = wid & 1;
        float cS[2][8][4];
        #pragma unroll
        for (int mi = 0; mi < 2; mi++)
            #pragma unroll
            for (int nj = 0; nj < 8; nj++)
                #pragma unroll
                for (int q = 0; q < 4; q++) cS[mi][nj][q] = 0.f;

        #pragma unroll
        for (int kk = 0; kk < 8; kk++) {
            int kc = kk * 8 + tg;
            uint32_t a[2][4];
            #pragma unroll
            for (int mi = 0; mi < 2; mi++) {
                int ar = r0 + mi * 16;
                a[mi][0] = __float_as_uint(sq[(ar + gid) * SA + kc]);
                a[mi][1] = __float_as_uint(sq[(ar + 8 + gid) * SA + kc]);
                a[mi][2] = __float_as_uint(sq[(ar + gid) * SA + kc + 4]);
                a[mi][3] = __float_as_uint(sq[(ar + 8 + gid) * SA + kc + 4]);
            }
            #pragma unroll
            for (int nj = 0; nj < 8; nj++) {
                uint32_t b0 = __float_as_uint(sk[(cN0 + nj * 8 + gid) * SA + kc]);
                uint32_t b1 = __float_as_uint(sk[(cN0 + nj * 8 + gid) * SA + kc + 4]);
                mma8(cS[0][nj], a[0][0], a[0][1], a[0][2], a[0][3], b0, b1);
                mma8(cS[1][nj], a[1][0], a[1][1], a[1][2], a[1][3], b0, b1);
            }
        }

        // mask, rowsum partials, store masked S (tf32) to smem
        #pragma unroll
        for (int mi = 0; mi < 2; mi++) {
            int rlo = r0 + mi * 16 + gid, rhi = rlo + 8;
            float zlo = 0.f, zhi = 0.f;
            #pragma unroll
            for (int nj = 0; nj < 8; nj++) {
                int c0 = cN0 + nj * 8 + 2 * tg, c1 = c0 + 1;
                float s0 = (c0 <= rlo) ? cS[mi][nj][0] : 0.f;
                float s1 = (c1 <= rlo) ? cS[mi][nj][1] : 0.f;
                float s2 = (c0 <= rhi) ? cS[mi][nj][2] : 0.f;
                float s3 = (c1 <= rhi) ? cS[mi][nj][3] : 0.f;
                zlo += s0 + s1;
                zhi += s2 + s3;
                *(float2*)&sS[rlo * SSW + c0] = make_float2(f2tf(s0), f2tf(s1));
                *(float2*)&sS[rhi * SSW + c0] = make_float2(f2tf(s2), f2tf(s3));
            }
            zlo += __shfl_xor_sync(0xffffffffu, zlo, 1);
            zlo += __shfl_xor_sync(0xffffffffu, zlo, 2);
            zhi += __shfl_xor_sync(0xffffffffu, zhi, 1);
            zhi += __shfl_xor_sync(0xffffffffu, zhi, 2);
            if (tg == 0) {
                szp[wn * CC + rlo] = zlo;
                szp[wn * CC + rhi] = zhi;
            }
        }
    } else {
        // ---- O_inter = phi(q) @ kvp : warp tile 32 x 32, K=64 ----
        #pragma unroll
        for (int mi = 0; mi < 2; mi++)
            #pragma unroll
            for (int nj = 0; nj < 4; nj++)
                #pragma unroll
                for (int q = 0; q < 4; q++) cO[mi][nj][q] = 0.f;

        #pragma unroll
        for (int kk = 0; kk < 8; kk++) {
            int kc = kk * 8 + tg;
            uint32_t a[2][4];
            #pragma unroll
            for (int mi = 0; mi < 2; mi++) {
                int ar = rq0 + mi * 16;
                a[mi][0] = __float_as_uint(sq[(ar + gid) * SA + kc]);
                a[mi][1] = __float_as_uint(sq[(ar + 8 + gid) * SA + kc]);
                a[mi][2] = __float_as_uint(sq[(ar + gid) * SA + kc + 4]);
                a[mi][3] = __float_as_uint(sq[(ar + 8 + gid) * SA + kc + 4]);
            }
            #pragma unroll
            for (int nj = 0; nj < 4; nj++) {
                uint32_t b0 = __float_as_uint(skvp[kc * SB + ocq + nj * 8 + gid]);
                uint32_t b1 = __float_as_uint(skvp[(kc + 4) * SB + ocq + nj * 8 + gid]);
                mma8(cO[0][nj], a[0][0], a[0][1], a[0][2], a[0][3], b0, b1);
                mma8(cO[1][nj], a[1][0], a[1][1], a[1][2], a[1][3], b0, b1);
            }
        }
    }
    __syncthreads();   // (B): masked S + szp visible; inter GEMM done

    if (wid < 8) {
        // ---- z[l] = rowsums + q . ksum_prev + eps (warps 0-3) ----
        if (tid < CC) {
            float qd = EPS;
            #pragma unroll 8
            for (int d = 0; d < DD; d++) qd += sq[tid * SA + d] * sksp[d];
            sz[tid] = szp[tid] + szp[CC + tid] + qd;
        }
    } else {
        // ---- O += S_masked @ V : K=128 ----
        #pragma unroll
        for (int kk = 0; kk < 16; kk++) {
            int kc = kk * 8 + tg;
            uint32_t a[2][4];
            #pragma unroll
            for (int mi = 0; mi < 2; mi++) {
                int ar = rq0 + mi * 16;
                a[mi][0] = __float_as_uint(sS[(ar + gid) * SSW + kc]);
                a[mi][1] = __float_as_uint(sS[(ar + 8 + gid) * SSW + kc]);
                a[mi][2] = __float_as_uint(sS[(ar + gid) * SSW + kc + 4]);
                a[mi][3] = __float_as_uint(sS[(ar + 8 + gid) * SSW + kc + 4]);
            }
            #pragma unroll
            for (int nj = 0; nj < 4; nj++) {
                uint32_t b0 = __float_as_uint(sv[kc * SB + ocq + nj * 8 + gid]);
                uint32_t b1 = __float_as_uint(sv[(kc + 4) * SB + ocq + nj * 8 + gid]);
                mma8(cO[0][nj], a[0][0], a[0][1], a[0][2], a[0][3], b0, b1);
                mma8(cO[1][nj], a[1][0], a[1][1], a[1][2], a[1][3], b0, b1);
            }
        }
    }
    __syncthreads();   // (C): sz visible

    if (wid >= 8) {
        // ---- epilogue: divide by z, store ----
        #pragma unroll
        for (int mi = 0; mi < 2; mi++) {
            int rlo = rq0 + mi * 16 + gid, rhi = rlo + 8;
            float izlo = 1.f / sz[rlo];
            float izhi = 1.f / sz[rhi];
            float* oblo = O + ((size_t)((n * LL + g * CC + rlo) * HH + h)) * MM;
            float* obhi = O + ((size_t)((n * LL + g * CC + rhi) * HH + h)) * MM;
            #pragma unroll
            for (int nj = 0; nj < 4; nj++) {
                int c0 = ocq + nj * 8 + 2 * tg;
                *(float2*)(oblo + c0) = make_float2(cO[mi][nj][0] * izlo, cO[mi][nj][1] * izlo);
                *(float2*)(obhi + c0) = make_float2(cO[mi][nj][2] * izhi, cO[mi][nj][3] * izhi);
            }
        }
    }
}

// ---------------------------------------------------------------------------
extern "C" void kernel_launch(void* const* d_in, const int* in_sizes, int n_in,
                              void* d_out, int out_size) {
    const float* Q = (const float*)d_in[0];
    const float* K = (const float*)d_in[1];
    const float* V = (const float*)d_in[2];
    float* O = (float*)d_out;

    cudaFuncSetAttribute(k_state, cudaFuncAttributeMaxDynamicSharedMemorySize, SMEM1);
    cudaFuncSetAttribute(k_main,  cudaFuncAttributeMaxDynamicSharedMemorySize, SMEM3);

    k_state<<<NTILE, 256, SMEM1>>>(K, V);
    k_scan<<<dim3(NB * HH, 4), 256>>>();
    k_main<<<NTILE, 512, SMEM3>>>(Q, K, V, O);
}